// round 2
// baseline (speedup 1.0000x reference)
#include <cuda_runtime.h>

// Problem constants
#define B_   2
#define S_   2048
#define H_   1024
#define NH_  16
#define HD_  64
#define M_   (B_*S_)        // 4096 rows of x
#define SCALE_ 0.125f       // HD^-0.5

// Scratch (allocation is forbidden -> device globals)
__device__ float g_q [B_*NH_*S_*HD_];   // [B,NH,S,HD]
__device__ float g_k [B_*NH_*S_*HD_];
__device__ float g_v [B_*NH_*S_*HD_];
__device__ float g_ao[B_*S_*H_];        // attention output, [B,S,H]

// ---------------------------------------------------------------------------
// GEMM 1: qkv = x @ w_qkv + b_qkv, scattered into head-major q/k/v
// M=4096, N=3072, K=1024.  128x128 tile, BK=8, 256 threads, 8x8 microtile.
// ---------------------------------------------------------------------------
__global__ __launch_bounds__(256) void qkv_gemm_kernel(
    const float* __restrict__ X, const float* __restrict__ W,
    const float* __restrict__ bias)
{
    const int K = H_;       // 1024
    const int N = 3*H_;     // 3072
    __shared__ float As[8][128];
    __shared__ float Bs[8][128];

    int tid = threadIdx.x;
    int bm = blockIdx.y, bn = blockIdx.x;
    int tx = tid & 15, ty = tid >> 4;

    int a_row = tid >> 1;           // 0..127
    int a_col = (tid & 1) * 4;      // 0 or 4
    int b_row = tid >> 5;           // 0..7
    int b_col = (tid & 31) * 4;     // 0..124

    const float* Aptr = X + (size_t)(bm*128 + a_row)*K + a_col;
    const float* Bptr = W + (size_t)b_row*N + bn*128 + b_col;

    float acc[8][8];
    #pragma unroll
    for (int i = 0; i < 8; i++)
        #pragma unroll
        for (int j = 0; j < 8; j++) acc[i][j] = 0.f;

    for (int k0 = 0; k0 < K; k0 += 8) {
        float4 av = *(const float4*)(Aptr + k0);
        float4 bv = *(const float4*)(Bptr + (size_t)k0*N);
        As[a_col+0][a_row] = av.x;
        As[a_col+1][a_row] = av.y;
        As[a_col+2][a_row] = av.z;
        As[a_col+3][a_row] = av.w;
        *(float4*)&Bs[b_row][b_col] = bv;
        __syncthreads();
        #pragma unroll
        for (int k = 0; k < 8; k++) {
            float4 a0 = *(const float4*)&As[k][ty*8];
            float4 a1 = *(const float4*)&As[k][ty*8+4];
            float4 b0 = *(const float4*)&Bs[k][tx*8];
            float4 b1 = *(const float4*)&Bs[k][tx*8+4];
            float af[8] = {a0.x,a0.y,a0.z,a0.w,a1.x,a1.y,a1.z,a1.w};
            float bf[8] = {b0.x,b0.y,b0.z,b0.w,b1.x,b1.y,b1.z,b1.w};
            #pragma unroll
            for (int i = 0; i < 8; i++)
                #pragma unroll
                for (int j = 0; j < 8; j++)
                    acc[i][j] += af[i]*bf[j];
        }
        __syncthreads();
    }

    // Epilogue: add bias, scatter into q/k/v [B,NH,S,HD]
    #pragma unroll
    for (int i = 0; i < 8; i++) {
        int m = bm*128 + ty*8 + i;
        int b = m / S_, s = m % S_;
        #pragma unroll
        for (int j = 0; j < 8; j++) {
            int n = bn*128 + tx*8 + j;
            float val = acc[i][j] + bias[n];
            int which = n >> 10;          // 0=q,1=k,2=v
            int h = (n & 1023) >> 6;
            int d = n & 63;
            float* dst = (which == 0) ? g_q : (which == 1) ? g_k : g_v;
            dst[((size_t)(b*NH_ + h)*S_ + s)*HD_ + d] = val;
        }
    }
}

// ---------------------------------------------------------------------------
// GEMM 2 (last): out = g_ao @ w_out + b_out   (M=4096, N=1024, K=1024)
// ---------------------------------------------------------------------------
__global__ __launch_bounds__(256) void out_gemm_kernel(
    const float* __restrict__ W, const float* __restrict__ bias,
    float* __restrict__ C)
{
    const int K = H_;   // 1024
    const int N = H_;   // 1024
    const float* X = g_ao;
    __shared__ float As[8][128];
    __shared__ float Bs[8][128];

    int tid = threadIdx.x;
    int bm = blockIdx.y, bn = blockIdx.x;
    int tx = tid & 15, ty = tid >> 4;

    int a_row = tid >> 1;
    int a_col = (tid & 1) * 4;
    int b_row = tid >> 5;
    int b_col = (tid & 31) * 4;

    const float* Aptr = X + (size_t)(bm*128 + a_row)*K + a_col;
    const float* Bptr = W + (size_t)b_row*N + bn*128 + b_col;

    float acc[8][8];
    #pragma unroll
    for (int i = 0; i < 8; i++)
        #pragma unroll
        for (int j = 0; j < 8; j++) acc[i][j] = 0.f;

    for (int k0 = 0; k0 < K; k0 += 8) {
        float4 av = *(const float4*)(Aptr + k0);
        float4 bv = *(const float4*)(Bptr + (size_t)k0*N);
        As[a_col+0][a_row] = av.x;
        As[a_col+1][a_row] = av.y;
        As[a_col+2][a_row] = av.z;
        As[a_col+3][a_row] = av.w;
        *(float4*)&Bs[b_row][b_col] = bv;
        __syncthreads();
        #pragma unroll
        for (int k = 0; k < 8; k++) {
            float4 a0 = *(const float4*)&As[k][ty*8];
            float4 a1 = *(const float4*)&As[k][ty*8+4];
            float4 b0 = *(const float4*)&Bs[k][tx*8];
            float4 b1 = *(const float4*)&Bs[k][tx*8+4];
            float af[8] = {a0.x,a0.y,a0.z,a0.w,a1.x,a1.y,a1.z,a1.w};
            float bf[8] = {b0.x,b0.y,b0.z,b0.w,b1.x,b1.y,b1.z,b1.w};
            #pragma unroll
            for (int i = 0; i < 8; i++)
                #pragma unroll
                for (int j = 0; j < 8; j++)
                    acc[i][j] += af[i]*bf[j];
        }
        __syncthreads();
    }

    #pragma unroll
    for (int i = 0; i < 8; i++) {
        int m = bm*128 + ty*8 + i;
        #pragma unroll
        for (int j = 0; j < 8; j++) {
            int n = bn*128 + tx*8 + j;
            C[(size_t)m*N + n] = acc[i][j] + bias[n];
        }
    }
}

// ---------------------------------------------------------------------------
// Attention: flash-style online softmax, full (non-causal).
// One block = 64 query rows of one (b,h). One thread per query row.
// ---------------------------------------------------------------------------
#define QB 64
#define KB 32

__global__ __launch_bounds__(64) void attn_kernel()
{
    __shared__ float q_sh[QB][HD_ + 1];   // padded: conflict-free per-lane row reads
    __shared__ float k_sh[KB*HD_];
    __shared__ float v_sh[KB*HD_];

    int t  = threadIdx.x;       // query row within tile (0..63)
    int qt = blockIdx.x;        // 0..31 query tiles
    int bh = blockIdx.y;        // 0..31 (b*NH + h)

    const float* qbase = g_q + ((size_t)bh*S_ + qt*QB)*HD_;
    const float* kbase = g_k + (size_t)bh*S_*HD_;
    const float* vbase = g_v + (size_t)bh*S_*HD_;

    // load Q tile (contiguous 4096 floats), store padded
    for (int i = t*4; i < QB*HD_; i += 64*4) {
        float4 v4 = *(const float4*)(qbase + i);
        int r = i >> 6, d = i & 63;
        q_sh[r][d+0] = v4.x; q_sh[r][d+1] = v4.y;
        q_sh[r][d+2] = v4.z; q_sh[r][d+3] = v4.w;
    }

    float o[HD_];
    #pragma unroll
    for (int d = 0; d < HD_; d++) o[d] = 0.f;
    float mval = -1e30f, lval = 0.f;
    __syncthreads();

    for (int kt = 0; kt < S_; kt += KB) {
        // load K/V tiles (each KB*HD = 2048 contiguous floats)
        for (int i = t*4; i < KB*HD_; i += 64*4) {
            *(float4*)&k_sh[i] = *(const float4*)(kbase + kt*HD_ + i);
            *(float4*)&v_sh[i] = *(const float4*)(vbase + kt*HD_ + i);
        }
        __syncthreads();

        // scores: sc[j] = q_row . k_j
        float sc[KB];
        #pragma unroll
        for (int j = 0; j < KB; j++) sc[j] = 0.f;
        #pragma unroll 1
        for (int dc = 0; dc < HD_; dc += 16) {
            float qf[16];
            #pragma unroll
            for (int d = 0; d < 16; d++) qf[d] = q_sh[t][dc + d];
            #pragma unroll
            for (int j = 0; j < KB; j++)
                #pragma unroll
                for (int d = 0; d < 16; d++)
                    sc[j] += qf[d] * k_sh[j*HD_ + dc + d];
        }

        // online softmax update
        float mnew = mval;
        #pragma unroll
        for (int j = 0; j < KB; j++) {
            sc[j] *= SCALE_;
            mnew = fmaxf(mnew, sc[j]);
        }
        float corr = __expf(mval - mnew);
        mval = mnew;
        float psum = 0.f;
        #pragma unroll
        for (int j = 0; j < KB; j++) {
            sc[j] = __expf(sc[j] - mnew);
            psum += sc[j];
        }
        lval = lval*corr + psum;
        #pragma unroll
        for (int d = 0; d < HD_; d++) o[d] *= corr;

        // o += p @ V
        #pragma unroll
        for (int j = 0; j < KB; j++)
            #pragma unroll
            for (int d = 0; d < HD_; d++)
                o[d] += sc[j] * v_sh[j*HD_ + d];

        __syncthreads();
    }

    // normalize and stage through shared for coalesced [B,S,H] write
    float inv = 1.f / lval;
    #pragma unroll
    for (int d = 0; d < HD_; d++) q_sh[t][d] = o[d]*inv;
    __syncthreads();

    int b = bh >> 4, h = bh & 15;
    float* obase = g_ao + ((size_t)b*S_ + qt*QB)*H_ + h*HD_;
    for (int i = t*4; i < QB*HD_; i += 64*4) {
        int r = i >> 6, d = i & 63;
        float4 v4 = make_float4(q_sh[r][d], q_sh[r][d+1], q_sh[r][d+2], q_sh[r][d+3]);
        *(float4*)(obase + (size_t)r*H_ + d) = v4;
    }
}

// ---------------------------------------------------------------------------
// Launch
// ---------------------------------------------------------------------------
extern "C" void kernel_launch(void* const* d_in, const int* in_sizes, int n_in,
                              void* d_out, int out_size)
{
    const float* x     = (const float*)d_in[0];   // [B,S,H]
    const float* w_qkv = (const float*)d_in[1];   // [H,3H]
    const float* b_qkv = (const float*)d_in[2];   // [3H]
    const float* w_out = (const float*)d_in[3];   // [H,H]
    const float* b_out = (const float*)d_in[4];   // [H]
    float* out = (float*)d_out;                   // [B,S,H]

    // qkv projection + head scatter:  grid (N/128, M/128)
    qkv_gemm_kernel<<<dim3(3*H_/128, M_/128), 256>>>(x, w_qkv, b_qkv);

    // attention: grid (S/QB, B*NH)
    attn_kernel<<<dim3(S_/QB, B_*NH_), 64>>>();

    // output projection
    out_gemm_kernel<<<dim3(H_/128, M_/128), 256>>>(w_out, b_out, out);
}